// round 1
// baseline (speedup 1.0000x reference)
#include <cuda_runtime.h>
#include <math.h>

#define IN_F 768
#define HID  128
#define GPB  4          // graphs per block in epilogue

// Scratch (no allocations allowed): per-graph feature sums + tiny precomputed vectors
__device__ float g_S[1024 * IN_F];    // [G, 768] per-graph sum of x
__device__ float g_Cvec[HID];         // constant part of layer-1 prompt pre-activation
__device__ float g_M[HID * 2];        // M = W2 @ Wfc   [128,2]
__device__ float g_q[4];              // q[k*2+j] constant logit part per class node

// Graph norm constants (leaf/class deg=2, prompt deg=259):
//   dinv_n = dinv_c = 1/sqrt(2), dinv_p = 1/sqrt(259)
//   c_np = c_cp = 1/sqrt(518), c_pp = 1/259
#define C_NP (rsqrtf(518.0f))
#define C_PP (1.0f / 259.0f)

// ---------------------------------------------------------------------------
// K0: one block, 128 threads. All per-graph-invariant quantities.
// ---------------------------------------------------------------------------
__global__ void k0_const(const float* __restrict__ prompt,
                         const float* __restrict__ cls,     // [2,768]
                         const float* __restrict__ W1,      // [768,128]
                         const float* __restrict__ b1,
                         const float* __restrict__ W2,      // [128,128]
                         const float* __restrict__ b2,
                         const float* __restrict__ Wfc,     // [128,2]
                         const float* __restrict__ bfc)
{
    __shared__ float s_r1c0[HID], s_r1c1[HID], s_a0[HID], s_a1[HID];
    int h = threadIdx.x;   // 0..127

    // h0 projections of prompt + 2 class nodes
    float hp = 0.f, h0 = 0.f, h1 = 0.f;
    for (int f = 0; f < IN_F; ++f) {
        float w = W1[f * HID + h];
        hp = fmaf(prompt[f], w, hp);
        h0 = fmaf(cls[f], w, h0);
        h1 = fmaf(cls[IN_F + f], w, h1);
    }
    float bb = b1[h];
    // constant part of agg1_prompt (everything except c_np * (sum_x @ W1))
    g_Cvec[h] = C_NP * (h0 + h1) + C_PP * hp + bb;
    // layer-1 class embeddings (graph-invariant), relu'd
    s_r1c0[h] = fmaxf(C_NP * hp + 0.5f * h0 + bb, 0.f);
    s_r1c1[h] = fmaxf(C_NP * hp + 0.5f * h1 + bb, 0.f);

    // M = W2 @ Wfc  (row h)
    float m0 = 0.f, m1 = 0.f;
    for (int h2 = 0; h2 < HID; ++h2) {
        float w2 = W2[h * HID + h2];
        m0 = fmaf(w2, Wfc[h2 * 2 + 0], m0);
        m1 = fmaf(w2, Wfc[h2 * 2 + 1], m1);
    }
    g_M[h * 2 + 0] = m0;
    g_M[h * 2 + 1] = m1;
    __syncthreads();

    // z_k = r1c_k @ W2 (thread index = output column h)
    float z0 = 0.f, z1 = 0.f;
    for (int hh = 0; hh < HID; ++hh) {
        float w2 = W2[hh * HID + h];
        z0 = fmaf(s_r1c0[hh], w2, z0);
        z1 = fmaf(s_r1c1[hh], w2, z1);
    }
    float b2h = b2[h];
    s_a0[h] = 0.5f * z0 + b2h;   // dinv_c^2 * z + b2
    s_a1[h] = 0.5f * z1 + b2h;
    __syncthreads();

    // q_k[j] = a_k @ Wfc[:,j] + bfc[j]
    if (h < 4) {
        int k = h >> 1, j = h & 1;
        const float* a = k ? s_a1 : s_a0;
        float q = 0.f;
        for (int hh = 0; hh < HID; ++hh) q = fmaf(a[hh], Wfc[hh * 2 + j], q);
        g_q[h] = q + bfc[j];
    }
}

// ---------------------------------------------------------------------------
// K1: the HBM-bound kernel. One block per graph, 192 threads.
// Each thread owns one float4 column (768/4 = 192) and sums 256 rows.
// ---------------------------------------------------------------------------
__global__ void k1_reduce(const float* __restrict__ x, int nper)
{
    int g = blockIdx.x;
    int t = threadIdx.x;  // 0..191
    const float4* p = reinterpret_cast<const float4*>(x)
                      + (size_t)g * nper * (IN_F / 4) + t;
    float4 acc = make_float4(0.f, 0.f, 0.f, 0.f);
#pragma unroll 8
    for (int r = 0; r < nper; ++r) {
        float4 v = p[(size_t)r * (IN_F / 4)];
        acc.x += v.x; acc.y += v.y; acc.z += v.z; acc.w += v.w;
    }
    reinterpret_cast<float4*>(g_S)[(size_t)g * (IN_F / 4) + t] = acc;
}

// ---------------------------------------------------------------------------
// K2: per-graph S @ W1, relu epilogue, logits + log_softmax.
// 256 threads: 2 groups x 128 h-columns; 4 graphs per block.
// ---------------------------------------------------------------------------
__global__ void k2_epi(const float* __restrict__ W1, float* __restrict__ out)
{
    __shared__ float sS[GPB][IN_F];
    __shared__ float red[GPB][4][2];

    int gbase = blockIdx.x * GPB;
    int tid   = threadIdx.x;          // 0..255
    int grp   = tid >> 7;             // 0/1: which pair of graphs
    int h     = tid & 127;

    // cooperative load of 4 graph sums into smem (12 KB)
    {
        const float4* src = reinterpret_cast<const float4*>(g_S)
                            + (size_t)gbase * (IN_F / 4);
        float4* dst = reinterpret_cast<float4*>(&sS[0][0]);
        for (int i = tid; i < GPB * (IN_F / 4); i += blockDim.x) dst[i] = src[i];
    }
    __syncthreads();

    int s0 = grp * 2, s1 = grp * 2 + 1;
    float a0 = 0.f, a1 = 0.f;
#pragma unroll 4
    for (int f = 0; f < IN_F; ++f) {
        float w = W1[f * HID + h];
        a0 = fmaf(sS[s0][f], w, a0);
        a1 = fmaf(sS[s1][f], w, a1);
    }

    float Cv = g_Cvec[h];
    float m0 = g_M[h * 2 + 0], m1 = g_M[h * 2 + 1];
    float r0 = fmaxf(C_NP * a0 + Cv, 0.f);
    float r1 = fmaxf(C_NP * a1 + Cv, 0.f);
    float u00 = r0 * m0, u01 = r0 * m1;
    float u10 = r1 * m0, u11 = r1 * m1;

    // warp butterfly reduce over h
#pragma unroll
    for (int o = 16; o > 0; o >>= 1) {
        u00 += __shfl_down_sync(0xffffffffu, u00, o);
        u01 += __shfl_down_sync(0xffffffffu, u01, o);
        u10 += __shfl_down_sync(0xffffffffu, u10, o);
        u11 += __shfl_down_sync(0xffffffffu, u11, o);
    }
    int warp = tid >> 5;
    int lane = tid & 31;
    int wg   = warp & 3;              // warp-in-group (4 warps per group)
    if (lane == 0) {
        red[s0][wg][0] = u00; red[s0][wg][1] = u01;
        red[s1][wg][0] = u10; red[s1][wg][1] = u11;
    }
    __syncthreads();

    if (tid < GPB) {
        int s = tid;
        float u0 = red[s][0][0] + red[s][1][0] + red[s][2][0] + red[s][3][0];
        float u1 = red[s][0][1] + red[s][1][1] + red[s][2][1] + red[s][3][1];
        int g = gbase + s;
#pragma unroll
        for (int k = 0; k < 2; ++k) {
            float l0 = C_NP * u0 + g_q[k * 2 + 0];
            float l1 = C_NP * u1 + g_q[k * 2 + 1];
            float mx = fmaxf(l0, l1);
            float lse = mx + logf(expf(l0 - mx) + expf(l1 - mx));
            out[(g * 2 + k) * 2 + 0] = l0 - lse;
            out[(g * 2 + k) * 2 + 1] = l1 - lse;
        }
    }
}

// ---------------------------------------------------------------------------
extern "C" void kernel_launch(void* const* d_in, const int* in_sizes, int n_in,
                              void* d_out, int out_size)
{
    const float* x      = (const float*)d_in[0];
    const float* prompt = (const float*)d_in[1];
    const float* cls    = (const float*)d_in[2];
    const float* W1     = (const float*)d_in[3];
    const float* b1     = (const float*)d_in[4];
    const float* W2     = (const float*)d_in[5];
    const float* b2     = (const float*)d_in[6];
    const float* Wfc    = (const float*)d_in[7];
    const float* bfc    = (const float*)d_in[8];

    int G     = out_size / 4;                 // G * n_cls(2) * 2 logits
    int Nrows = in_sizes[0] / IN_F;
    int nper  = Nrows / G;                    // 256

    k0_const<<<1, 128>>>(prompt, cls, W1, b1, W2, b2, Wfc, bfc);
    k1_reduce<<<G, 192>>>(x, nper);
    k2_epi<<<G / GPB, 256>>>(W1, (float*)d_out);
}

// round 2
// speedup vs baseline: 1.1737x; 1.1737x over previous
#include <cuda_runtime.h>
#include <math.h>

#define IN_F 768
#define HID  128
#define GPB  8          // graphs per block in epilogue
#define NPART 48        // projection partial blocks (768/16)

// Scratch (no allocations allowed)
__device__ float g_S[1024 * IN_F];        // [G, 768] per-graph sum of x
__device__ float g_part[NPART][3][HID];   // partial projections hp/h0/h1
__device__ float g_Cvec[HID];             // constant part of layer-1 prompt pre-act
__device__ float g_M[HID * 2];            // M = W2 @ Wfc
__device__ float g_q[4];                  // constant logit part per class node

// Star-graph norm constants: leaf/class deg=2, prompt deg=259
#define C_NP (rsqrtf(518.0f))
#define C_PP (1.0f / 259.0f)

// ---------------------------------------------------------------------------
// K0a: 48 blocks x 128 threads. Partial projections of prompt + 2 class nodes
// through W1. Block b owns f in [16b, 16b+16).
// ---------------------------------------------------------------------------
__global__ void k0a_proj(const float* __restrict__ prompt,
                         const float* __restrict__ cls,
                         const float* __restrict__ W1)
{
    int b = blockIdx.x;
    int h = threadIdx.x;
    int f0 = b * 16;
    float hp = 0.f, h0 = 0.f, h1 = 0.f;
#pragma unroll
    for (int i = 0; i < 16; ++i) {
        int f = f0 + i;
        float w = W1[f * HID + h];
        hp = fmaf(__ldg(&prompt[f]),      w, hp);
        h0 = fmaf(__ldg(&cls[f]),         w, h0);
        h1 = fmaf(__ldg(&cls[IN_F + f]),  w, h1);
    }
    g_part[b][0][h] = hp;
    g_part[b][1][h] = h0;
    g_part[b][2][h] = h1;
}

// ---------------------------------------------------------------------------
// K0b: 1 block, 512 threads. Finishes all graph-invariant constants with
// warp-level parallelism (no long serial latency chains).
// ---------------------------------------------------------------------------
__global__ void k0b_const(const float* __restrict__ b1,
                          const float* __restrict__ W2,
                          const float* __restrict__ b2,
                          const float* __restrict__ Wfc,
                          const float* __restrict__ bfc)
{
    __shared__ float s_r1c[2][HID];
    __shared__ float s_a2[2][HID];
    __shared__ float s_redq[2][2][4];

    int tid = threadIdx.x;

    // Phase 1: threads 0..127 sum partials, compute Cvec + relu'd class embs
    if (tid < HID) {
        int h = tid;
        float hp = 0.f, h0 = 0.f, h1 = 0.f;
#pragma unroll 8
        for (int b = 0; b < NPART; ++b) {
            hp += g_part[b][0][h];
            h0 += g_part[b][1][h];
            h1 += g_part[b][2][h];
        }
        float bb = b1[h];
        g_Cvec[h]   = C_NP * (h0 + h1) + C_PP * hp + bb;
        s_r1c[0][h] = fmaxf(C_NP * hp + 0.5f * h0 + bb, 0.f);
        s_r1c[1][h] = fmaxf(C_NP * hp + 0.5f * h1 + bb, 0.f);
    }
    __syncthreads();

    // Phase 2 (threads 0..255): z_k[h] = r1c_k @ W2[:,h]; a2 = 0.5 z + b2
    if (tid < 256) {
        int k = tid >> 7, h = tid & 127;
        float z = 0.f;
#pragma unroll 8
        for (int hh = 0; hh < HID; ++hh)
            z = fmaf(s_r1c[k][hh], W2[hh * HID + h], z);
        s_a2[k][h] = 0.5f * z + b2[h];
    }
    // Phase 3 (threads 256..383, concurrent): M[h] = W2[h,:] @ Wfc
    else if (tid < 384) {
        int h = tid - 256;
        float m0 = 0.f, m1 = 0.f;
#pragma unroll 8
        for (int h2 = 0; h2 < HID; ++h2) {
            float w2 = W2[h * HID + h2];
            m0 = fmaf(w2, Wfc[h2 * 2 + 0], m0);
            m1 = fmaf(w2, Wfc[h2 * 2 + 1], m1);
        }
        g_M[h * 2 + 0] = m0;
        g_M[h * 2 + 1] = m1;
    }
    __syncthreads();

    // Phase 4 (all 512 threads): q[k][j] = a2_k @ Wfc[:,j] + bfc[j]
    {
        int k = tid >> 8, j = (tid >> 7) & 1, h = tid & 127;
        float u = s_a2[k][h] * Wfc[h * 2 + j];
#pragma unroll
        for (int o = 16; o > 0; o >>= 1)
            u += __shfl_down_sync(0xffffffffu, u, o);
        if ((tid & 31) == 0)
            s_redq[k][j][(tid >> 5) & 3] = u;
    }
    __syncthreads();
    if (tid < 4) {
        int k = tid >> 1, j = tid & 1;
        g_q[tid] = s_redq[k][j][0] + s_redq[k][j][1] +
                   s_redq[k][j][2] + s_redq[k][j][3] + bfc[j];
    }
}

// ---------------------------------------------------------------------------
// K1: HBM-bound per-graph column-sum of x. 1024 blocks x 192 threads;
// thread t owns float4 column t, sums 256 rows.
// ---------------------------------------------------------------------------
__global__ void k1_reduce(const float* __restrict__ x, int nper)
{
    int g = blockIdx.x;
    int t = threadIdx.x;  // 0..191
    const float4* p = reinterpret_cast<const float4*>(x)
                      + (size_t)g * nper * (IN_F / 4) + t;
    float4 acc = make_float4(0.f, 0.f, 0.f, 0.f);
#pragma unroll 16
    for (int r = 0; r < nper; ++r) {
        float4 v = p[(size_t)r * (IN_F / 4)];
        acc.x += v.x; acc.y += v.y; acc.z += v.z; acc.w += v.w;
    }
    reinterpret_cast<float4*>(g_S)[(size_t)g * (IN_F / 4) + t] = acc;
}

// ---------------------------------------------------------------------------
// K2: per-graph S @ W1, relu, logits + log_softmax. 8 graphs/block,
// 512 threads (4 groups x 128 h-cols, 2 graphs per group), 128 blocks.
// ---------------------------------------------------------------------------
__global__ void __launch_bounds__(512)
k2_epi(const float* __restrict__ W1, float* __restrict__ out)
{
    __shared__ float sS[GPB][IN_F];       // 24 KB
    __shared__ float red[GPB][4][2];

    int gbase = blockIdx.x * GPB;
    int tid   = threadIdx.x;              // 0..511
    int grp   = tid >> 7;                 // 0..3: which pair of graphs
    int h     = tid & 127;

    // cooperative load of 8 graph sums into smem
    {
        const float4* src = reinterpret_cast<const float4*>(g_S)
                            + (size_t)gbase * (IN_F / 4);
        float4* dst = reinterpret_cast<float4*>(&sS[0][0]);
#pragma unroll
        for (int i = tid; i < GPB * (IN_F / 4); i += 512) dst[i] = src[i];
    }
    __syncthreads();

    int s0 = grp * 2, s1 = grp * 2 + 1;
    float a0 = 0.f, a1 = 0.f;
#pragma unroll 4
    for (int f = 0; f < IN_F; ++f) {
        float w = W1[f * HID + h];
        a0 = fmaf(sS[s0][f], w, a0);
        a1 = fmaf(sS[s1][f], w, a1);
    }

    float Cv = g_Cvec[h];
    float m0 = g_M[h * 2 + 0], m1 = g_M[h * 2 + 1];
    float r0 = fmaxf(C_NP * a0 + Cv, 0.f);
    float r1 = fmaxf(C_NP * a1 + Cv, 0.f);
    float u00 = r0 * m0, u01 = r0 * m1;
    float u10 = r1 * m0, u11 = r1 * m1;

#pragma unroll
    for (int o = 16; o > 0; o >>= 1) {
        u00 += __shfl_down_sync(0xffffffffu, u00, o);
        u01 += __shfl_down_sync(0xffffffffu, u01, o);
        u10 += __shfl_down_sync(0xffffffffu, u10, o);
        u11 += __shfl_down_sync(0xffffffffu, u11, o);
    }
    int warp = tid >> 5;
    int lane = tid & 31;
    int wg   = warp & 3;                  // warp-in-group
    if (lane == 0) {
        red[s0][wg][0] = u00; red[s0][wg][1] = u01;
        red[s1][wg][0] = u10; red[s1][wg][1] = u11;
    }
    __syncthreads();

    if (tid < GPB) {
        int s = tid;
        float u0 = red[s][0][0] + red[s][1][0] + red[s][2][0] + red[s][3][0];
        float u1 = red[s][0][1] + red[s][1][1] + red[s][2][1] + red[s][3][1];
        int g = gbase + s;
#pragma unroll
        for (int k = 0; k < 2; ++k) {
            float l0 = C_NP * u0 + g_q[k * 2 + 0];
            float l1 = C_NP * u1 + g_q[k * 2 + 1];
            float mx = fmaxf(l0, l1);
            float lse = mx + logf(expf(l0 - mx) + expf(l1 - mx));
            out[(g * 2 + k) * 2 + 0] = l0 - lse;
            out[(g * 2 + k) * 2 + 1] = l1 - lse;
        }
    }
}

// ---------------------------------------------------------------------------
extern "C" void kernel_launch(void* const* d_in, const int* in_sizes, int n_in,
                              void* d_out, int out_size)
{
    const float* x      = (const float*)d_in[0];
    const float* prompt = (const float*)d_in[1];
    const float* cls    = (const float*)d_in[2];
    const float* W1     = (const float*)d_in[3];
    const float* b1     = (const float*)d_in[4];
    const float* W2     = (const float*)d_in[5];
    const float* b2     = (const float*)d_in[6];
    const float* Wfc    = (const float*)d_in[7];
    const float* bfc    = (const float*)d_in[8];

    int G     = out_size / 4;                 // 1024
    int Nrows = in_sizes[0] / IN_F;
    int nper  = Nrows / G;                    // 256

    k0a_proj<<<NPART, 128>>>(prompt, cls, W1);
    k0b_const<<<1, 512>>>(b1, W2, b2, Wfc, bfc);
    k1_reduce<<<G, 192>>>(x, nper);
    k2_epi<<<G / GPB, 512>>>(W1, (float*)d_out);
}

// round 3
// speedup vs baseline: 1.5964x; 1.3602x over previous
#include <cuda_runtime.h>
#include <math.h>

#define IN_F 768
#define HID  128
#define GPB  8          // graphs per block in epilogue
#define NPART 48        // projection partial blocks

// Scratch (no allocations allowed)
__device__ float g_S[1024 * IN_F];        // [G, 768] per-graph sum of x
__device__ float g_part[NPART][3][HID];   // partial projections hp/h0/h1
__device__ float g_Cvec[HID];             // constant part of layer-1 prompt pre-act
__device__ float g_M[HID * 2];            // M = W2 @ Wfc
__device__ float g_q[4];                  // constant logit part per class node

// Star-graph norm constants: leaf/class deg=2, prompt deg=259
#define C_NP (rsqrtf(518.0f))
#define C_PP (1.0f / 259.0f)

// ---------------------------------------------------------------------------
// K0a: 48 blocks x 128 threads. Partial projections of prompt + 2 class nodes.
// ---------------------------------------------------------------------------
__global__ void k0a_proj(const float* __restrict__ prompt,
                         const float* __restrict__ cls,
                         const float* __restrict__ W1)
{
    int b = blockIdx.x;
    int h = threadIdx.x;
    int f0 = b * 16;
    float hp = 0.f, h0 = 0.f, h1 = 0.f;
#pragma unroll
    for (int i = 0; i < 16; ++i) {
        int f = f0 + i;
        float w = W1[f * HID + h];
        hp = fmaf(__ldg(&prompt[f]),      w, hp);
        h0 = fmaf(__ldg(&cls[f]),         w, h0);
        h1 = fmaf(__ldg(&cls[IN_F + f]),  w, h1);
    }
    g_part[b][0][h] = hp;
    g_part[b][1][h] = h0;
    g_part[b][2][h] = h1;
}

// ---------------------------------------------------------------------------
// K0b: 1 block, 512 threads. Finishes graph-invariant constants.
// ---------------------------------------------------------------------------
__global__ void k0b_const(const float* __restrict__ b1,
                          const float* __restrict__ W2,
                          const float* __restrict__ b2,
                          const float* __restrict__ Wfc,
                          const float* __restrict__ bfc)
{
    __shared__ float s_r1c[2][HID];
    __shared__ float s_a2[2][HID];
    __shared__ float s_redq[2][2][4];

    int tid = threadIdx.x;

    if (tid < HID) {
        int h = tid;
        float hp = 0.f, h0 = 0.f, h1 = 0.f;
#pragma unroll 8
        for (int b = 0; b < NPART; ++b) {
            hp += g_part[b][0][h];
            h0 += g_part[b][1][h];
            h1 += g_part[b][2][h];
        }
        float bb = b1[h];
        g_Cvec[h]   = C_NP * (h0 + h1) + C_PP * hp + bb;
        s_r1c[0][h] = fmaxf(C_NP * hp + 0.5f * h0 + bb, 0.f);
        s_r1c[1][h] = fmaxf(C_NP * hp + 0.5f * h1 + bb, 0.f);
    }
    __syncthreads();

    if (tid < 256) {
        int k = tid >> 7, h = tid & 127;
        float z = 0.f;
#pragma unroll 8
        for (int hh = 0; hh < HID; ++hh)
            z = fmaf(s_r1c[k][hh], W2[hh * HID + h], z);
        s_a2[k][h] = 0.5f * z + b2[h];
    } else if (tid < 384) {
        int h = tid - 256;
        float m0 = 0.f, m1 = 0.f;
#pragma unroll 8
        for (int h2 = 0; h2 < HID; ++h2) {
            float w2 = W2[h * HID + h2];
            m0 = fmaf(w2, Wfc[h2 * 2 + 0], m0);
            m1 = fmaf(w2, Wfc[h2 * 2 + 1], m1);
        }
        g_M[h * 2 + 0] = m0;
        g_M[h * 2 + 1] = m1;
    }
    __syncthreads();

    {
        int k = tid >> 8, j = (tid >> 7) & 1, h = tid & 127;
        float u = s_a2[k][h] * Wfc[h * 2 + j];
#pragma unroll
        for (int o = 16; o > 0; o >>= 1)
            u += __shfl_down_sync(0xffffffffu, u, o);
        if ((tid & 31) == 0)
            s_redq[k][j][(tid >> 5) & 3] = u;
    }
    __syncthreads();
    if (tid < 4) {
        int k = tid >> 1, j = tid & 1;
        g_q[tid] = s_redq[k][j][0] + s_redq[k][j][1] +
                   s_redq[k][j][2] + s_redq[k][j][3] + bfc[j];
    }
}

// ---------------------------------------------------------------------------
// K1: HBM-bound per-graph column-sum of x. 1024 blocks x 192 threads.
// ---------------------------------------------------------------------------
__global__ void k1_reduce(const float* __restrict__ x, int nper)
{
    int g = blockIdx.x;
    int t = threadIdx.x;
    const float4* p = reinterpret_cast<const float4*>(x)
                      + (size_t)g * nper * (IN_F / 4) + t;
    float4 acc = make_float4(0.f, 0.f, 0.f, 0.f);
#pragma unroll 16
    for (int r = 0; r < nper; ++r) {
        float4 v = p[(size_t)r * (IN_F / 4)];
        acc.x += v.x; acc.y += v.y; acc.z += v.z; acc.w += v.w;
    }
    reinterpret_cast<float4*>(g_S)[(size_t)g * (IN_F / 4) + t] = acc;
}

// ---------------------------------------------------------------------------
// K2: S @ W1 epilogue, restructured for ILP.
// 256 threads = 8 warps. Warp w owns f-slice [96w, 96w+96). Thread lane owns
// h-columns 4*lane..4*lane+3 (float4 W1 loads). 8 graphs per block = 8 float4
// accumulators per thread. Cross-warp reduction via aliased smem buffer.
// ---------------------------------------------------------------------------
__global__ void __launch_bounds__(256)
k2_epi(const float* __restrict__ W1, float* __restrict__ out)
{
    // buf aliased: phase 1 = sS[GPB][768] (24KB); phase 2 = part[8][GPB][128] (32KB)
    __shared__ float buf[8 * GPB * HID];   // 32 KB
    __shared__ float red[GPB][4][2];

    int tid  = threadIdx.x;
    int w    = tid >> 5;
    int lane = tid & 31;
    int gbase = blockIdx.x * GPB;

    // Phase 0: load 8 graph sums into smem
    {
        const float4* src = reinterpret_cast<const float4*>(g_S)
                            + (size_t)gbase * (IN_F / 4);
        float4* dst = reinterpret_cast<float4*>(buf);
#pragma unroll
        for (int i = tid; i < GPB * (IN_F / 4); i += 256) dst[i] = src[i];
    }
    __syncthreads();

    // Phase 1: warp-sliced GEMM. acc[g] = partial over this warp's f-range.
    float4 acc[GPB];
#pragma unroll
    for (int g = 0; g < GPB; ++g) acc[g] = make_float4(0.f, 0.f, 0.f, 0.f);

    const float4* Wp = reinterpret_cast<const float4*>(W1);
    int f0 = w * (IN_F / 8);   // 96 f's per warp
#pragma unroll 4
    for (int i = 0; i < IN_F / 8; ++i) {
        int f = f0 + i;
        float4 wv = Wp[f * 32 + lane];
#pragma unroll
        for (int g = 0; g < GPB; ++g) {
            float s = buf[g * IN_F + f];
            acc[g].x = fmaf(s, wv.x, acc[g].x);
            acc[g].y = fmaf(s, wv.y, acc[g].y);
            acc[g].z = fmaf(s, wv.z, acc[g].z);
            acc[g].w = fmaf(s, wv.w, acc[g].w);
        }
    }
    __syncthreads();   // all reads of sS done -> buf reusable as part[]

    // Phase 2: write partials. part[w][g][h], h = 4*lane+j, as float4 stores.
#pragma unroll
    for (int g = 0; g < GPB; ++g)
        reinterpret_cast<float4*>(buf)[(w * GPB + g) * 32 + lane] = acc[g];
    __syncthreads();

    // Phase 3: sum partials over 8 warps; relu + project to logits.
    int h   = tid & 127;
    int grp = tid >> 7;           // grp 0 -> graphs 0..3, grp 1 -> graphs 4..7
    int slot = w & 3;
    float Cv = g_Cvec[h];
    float m0 = g_M[2 * h], m1 = g_M[2 * h + 1];

#pragma unroll
    for (int gg = 0; gg < 4; ++gg) {
        int g = grp * 4 + gg;
        float a = 0.f;
#pragma unroll
        for (int ww = 0; ww < 8; ++ww)
            a += buf[(ww * GPB + g) * HID + h];
        float r = fmaxf(fmaf(C_NP, a, Cv), 0.f);
        float u0 = r * m0, u1 = r * m1;
#pragma unroll
        for (int o = 16; o > 0; o >>= 1) {
            u0 += __shfl_down_sync(0xffffffffu, u0, o);
            u1 += __shfl_down_sync(0xffffffffu, u1, o);
        }
        if (lane == 0) { red[g][slot][0] = u0; red[g][slot][1] = u1; }
    }
    __syncthreads();

    if (tid < GPB) {
        int g = tid;
        float u0 = red[g][0][0] + red[g][1][0] + red[g][2][0] + red[g][3][0];
        float u1 = red[g][0][1] + red[g][1][1] + red[g][2][1] + red[g][3][1];
        int gout = gbase + g;
#pragma unroll
        for (int k = 0; k < 2; ++k) {
            float l0 = C_NP * u0 + g_q[k * 2 + 0];
            float l1 = C_NP * u1 + g_q[k * 2 + 1];
            float mx = fmaxf(l0, l1);
            float lse = mx + logf(expf(l0 - mx) + expf(l1 - mx));
            out[(gout * 2 + k) * 2 + 0] = l0 - lse;
            out[(gout * 2 + k) * 2 + 1] = l1 - lse;
        }
    }
}

// ---------------------------------------------------------------------------
extern "C" void kernel_launch(void* const* d_in, const int* in_sizes, int n_in,
                              void* d_out, int out_size)
{
    const float* x      = (const float*)d_in[0];
    const float* prompt = (const float*)d_in[1];
    const float* cls    = (const float*)d_in[2];
    const float* W1     = (const float*)d_in[3];
    const float* b1     = (const float*)d_in[4];
    const float* W2     = (const float*)d_in[5];
    const float* b2     = (const float*)d_in[6];
    const float* Wfc    = (const float*)d_in[7];
    const float* bfc    = (const float*)d_in[8];

    int G     = out_size / 4;                 // 1024
    int Nrows = in_sizes[0] / IN_F;
    int nper  = Nrows / G;                    // 256

    k0a_proj<<<NPART, 128>>>(prompt, cls, W1);
    k0b_const<<<1, 512>>>(b1, W2, b2, Wfc, bfc);
    k1_reduce<<<G, 192>>>(x, nper);
    k2_epi<<<G / GPB, 256>>>(W1, (float*)d_out);
}